// round 1
// baseline (speedup 1.0000x reference)
#include <cuda_runtime.h>
#include <cuda_bf16.h>

// Problem dims (fixed by the dataset)
#define D_   3072
#define H_   1024
#define Z_   32
#define BS_  128
#define NN_  32
#define MNN  4096   // BS_*NN_
#define MALL 4224   // BS_ + MNN

// ---------------------------------------------------------------------------
// Static scratch (allocation-free rule: __device__ globals)
// ---------------------------------------------------------------------------
__device__ float g_h1[MALL * H_];     // encoder h1, later t_h1
__device__ float g_h2[MALL * H_];     // encoder h2, later t_h2
__device__ float g_Z[MALL * Z_];      // latent codes (rows 0..127 = z_c, rest z_nn)
__device__ float g_dz[MNN * Z_];      // z_nn - z_c
__device__ float g_h1c[BS_ * H_];     // decoder center h1 (relu'd; >0 == mask1)
__device__ float g_h2c[BS_ * H_];     // decoder center h2 (relu'd; >0 == mask2)
__device__ float g_recon[BS_ * D_];   // decoder center output
__device__ float g_w[MNN];            // binary kernel weights
__device__ float g_lpart[24 * 32];    // per-block loss partials (loss gemm grid)

// ---------------------------------------------------------------------------
// Tiled SGEMM: C(MxN) = A(MxK) @ B(KxN), all row-major.
// BM=BN=128, BK=8, 256 threads, 8x8 per thread.
// M = gridDim.y*128 (exact), N multiple of 128, K multiple of 8.
// EPI: 1 = +bias, relu; 2 = +bias; 3 = center-row mask (mask[(r>>5)*N+c] > 0)
// ---------------------------------------------------------------------------
template <int EPI>
__global__ void __launch_bounds__(256) gemm128(
    const float* __restrict__ A, const float* __restrict__ B,
    float* __restrict__ C, const float* __restrict__ bias,
    const float* __restrict__ mask, int K, int N)
{
    __shared__ float As[8][128];
    __shared__ float Bs[8][128];

    const int tid  = threadIdx.x;
    const int rb   = blockIdx.y * 128;
    const int cb   = blockIdx.x * 128;
    const int arow = tid >> 1;            // 0..127
    const int akc  = (tid & 1) * 4;       // 0 or 4
    const int brow = tid >> 5;            // 0..7
    const int bcol = (tid & 31) * 4;      // 0..124
    const int trow = (tid >> 4) * 8;      // 0..120
    const int tcol = (tid & 15) * 8;      // 0..120

    const float* Aptr = A + (size_t)(rb + arow) * K + akc;
    const float* Bptr = B + (size_t)brow * N + cb + bcol;

    float acc[8][8];
#pragma unroll
    for (int i = 0; i < 8; i++)
#pragma unroll
        for (int j = 0; j < 8; j++) acc[i][j] = 0.f;

    for (int kt = 0; kt < K; kt += 8) {
        float4 av = *(const float4*)(Aptr + kt);
        float4 bv = *(const float4*)(Bptr + (size_t)kt * N);
        __syncthreads();
        As[akc + 0][arow] = av.x;
        As[akc + 1][arow] = av.y;
        As[akc + 2][arow] = av.z;
        As[akc + 3][arow] = av.w;
        *(float4*)&Bs[brow][bcol] = bv;
        __syncthreads();
#pragma unroll
        for (int k = 0; k < 8; k++) {
            float4 a0 = *(const float4*)&As[k][trow];
            float4 a1 = *(const float4*)&As[k][trow + 4];
            float4 b0 = *(const float4*)&Bs[k][tcol];
            float4 b1 = *(const float4*)&Bs[k][tcol + 4];
            float ar[8] = {a0.x, a0.y, a0.z, a0.w, a1.x, a1.y, a1.z, a1.w};
            float br[8] = {b0.x, b0.y, b0.z, b0.w, b1.x, b1.y, b1.z, b1.w};
#pragma unroll
            for (int i = 0; i < 8; i++)
#pragma unroll
                for (int j = 0; j < 8; j++) acc[i][j] += ar[i] * br[j];
        }
    }

    const int cc = cb + tcol;
#pragma unroll
    for (int i = 0; i < 8; i++) {
        const int r = rb + trow + i;
        float o[8];
#pragma unroll
        for (int j = 0; j < 8; j++) o[j] = acc[i][j];
        if (EPI == 1 || EPI == 2) {
#pragma unroll
            for (int j = 0; j < 8; j++) o[j] += bias[cc + j];
            if (EPI == 1) {
#pragma unroll
                for (int j = 0; j < 8; j++) o[j] = fmaxf(o[j], 0.f);
            }
        } else if (EPI == 3) {
            const float* mr = mask + (size_t)(r >> 5) * N + cc;
#pragma unroll
            for (int j = 0; j < 8; j++) o[j] = (mr[j] > 0.f) ? o[j] : 0.f;
        }
        float4* Cp = (float4*)(C + (size_t)r * N + cc);
        Cp[0] = make_float4(o[0], o[1], o[2], o[3]);
        Cp[1] = make_float4(o[4], o[5], o[6], o[7]);
    }
}

// ---------------------------------------------------------------------------
// Same GEMM core but with the loss epilogue fused:
// jac = A@B ; e = x_nn - recon[b] - jac ; lpart += w[row]*e^2
// A = t_h2 (4096x1024), B = Wd3 (1024x3072). No bias (directional derivative).
// ---------------------------------------------------------------------------
__global__ void __launch_bounds__(256) gemm128_loss(
    const float* __restrict__ A, const float* __restrict__ B,
    const float* __restrict__ xnn, const float* __restrict__ recon,
    int K, int N)
{
    __shared__ float As[8][128];
    __shared__ float Bs[8][128];

    const int tid  = threadIdx.x;
    const int rb   = blockIdx.y * 128;
    const int cb   = blockIdx.x * 128;
    const int arow = tid >> 1;
    const int akc  = (tid & 1) * 4;
    const int brow = tid >> 5;
    const int bcol = (tid & 31) * 4;
    const int trow = (tid >> 4) * 8;
    const int tcol = (tid & 15) * 8;

    const float* Aptr = A + (size_t)(rb + arow) * K + akc;
    const float* Bptr = B + (size_t)brow * N + cb + bcol;

    float acc[8][8];
#pragma unroll
    for (int i = 0; i < 8; i++)
#pragma unroll
        for (int j = 0; j < 8; j++) acc[i][j] = 0.f;

    for (int kt = 0; kt < K; kt += 8) {
        float4 av = *(const float4*)(Aptr + kt);
        float4 bv = *(const float4*)(Bptr + (size_t)kt * N);
        __syncthreads();
        As[akc + 0][arow] = av.x;
        As[akc + 1][arow] = av.y;
        As[akc + 2][arow] = av.z;
        As[akc + 3][arow] = av.w;
        *(float4*)&Bs[brow][bcol] = bv;
        __syncthreads();
#pragma unroll
        for (int k = 0; k < 8; k++) {
            float4 a0 = *(const float4*)&As[k][trow];
            float4 a1 = *(const float4*)&As[k][trow + 4];
            float4 b0 = *(const float4*)&Bs[k][tcol];
            float4 b1 = *(const float4*)&Bs[k][tcol + 4];
            float ar[8] = {a0.x, a0.y, a0.z, a0.w, a1.x, a1.y, a1.z, a1.w};
            float br[8] = {b0.x, b0.y, b0.z, b0.w, b1.x, b1.y, b1.z, b1.w};
#pragma unroll
            for (int i = 0; i < 8; i++)
#pragma unroll
                for (int j = 0; j < 8; j++) acc[i][j] += ar[i] * br[j];
        }
    }

    const int cc = cb + tcol;
    float lsum = 0.f;
#pragma unroll
    for (int i = 0; i < 8; i++) {
        const int r = rb + trow + i;
        const int b = r >> 5;
        const float wr = g_w[r];
        const float* xr = xnn + (size_t)r * N + cc;
        const float* rr = recon + (size_t)b * N + cc;
        float4 x0 = *(const float4*)xr;
        float4 x1 = *(const float4*)(xr + 4);
        float4 r0 = *(const float4*)rr;
        float4 r1 = *(const float4*)(rr + 4);
        float xv[8] = {x0.x, x0.y, x0.z, x0.w, x1.x, x1.y, x1.z, x1.w};
        float rv[8] = {r0.x, r0.y, r0.z, r0.w, r1.x, r1.y, r1.z, r1.w};
#pragma unroll
        for (int j = 0; j < 8; j++) {
            float e = xv[j] - rv[j] - acc[i][j];
            lsum += wr * e * e;
        }
    }

    // block reduce (deterministic partials, no atomics)
#pragma unroll
    for (int o = 16; o; o >>= 1) lsum += __shfl_down_sync(0xffffffffu, lsum, o);
    __shared__ float red[8];
    if ((tid & 31) == 0) red[tid >> 5] = lsum;
    __syncthreads();
    if (tid == 0) {
        float t = 0.f;
#pragma unroll
        for (int i = 0; i < 8; i++) t += red[i];
        g_lpart[blockIdx.y * gridDim.x + blockIdx.x] = t;
    }
}

// ---------------------------------------------------------------------------
// Skinny GEMM for encoder layer 3: C(Mx32) = A(MxK) @ B(Kx32) + bias
// One output per thread; 8 rows x 32 cols per 256-thread block.
// ---------------------------------------------------------------------------
__global__ void __launch_bounds__(256) fc_skinny32(
    const float* __restrict__ A, const float* __restrict__ B,
    const float* __restrict__ bias, float* __restrict__ C, int K)
{
    const int r = blockIdx.x * 8 + (threadIdx.x >> 5);
    const int c = threadIdx.x & 31;
    const float* arow = A + (size_t)r * K;
    float s = 0.f;
#pragma unroll 8
    for (int k = 0; k < K; k++) s += __ldg(arow + k) * __ldg(B + (size_t)k * 32 + c);
    C[(size_t)r * 32 + c] = s + bias[c];
}

// dz[row][k] = z_nn[row][k] - z_c[row>>5][k]
__global__ void dz_kernel()
{
    const int i = blockIdx.x * 256 + threadIdx.x;  // 0 .. MNN*Z_-1
    const int row = i >> 5;
    const int k = i & 31;
    g_dz[i] = g_Z[(BS_ + row) * Z_ + k] - g_Z[(row >> 5) * Z_ + k];
}

// binary kernel weights: 1.0 if ||x_c[b]-x_nn[b,n]|| > 1e-12 else 0.5
__global__ void __launch_bounds__(128) weights_kernel(
    const float* __restrict__ xc, const float* __restrict__ xnn)
{
    const int row = blockIdx.x;
    const int b = row >> 5;
    const float4* a = (const float4*)(xc + (size_t)b * D_);
    const float4* x = (const float4*)(xnn + (size_t)row * D_);
    float s = 0.f;
    for (int d = threadIdx.x; d < D_ / 4; d += 128) {
        float4 av = a[d], xv = x[d];
        float dx = av.x - xv.x, dy = av.y - xv.y, dz2 = av.z - xv.z, dw = av.w - xv.w;
        s += dx * dx + dy * dy + dz2 * dz2 + dw * dw;
    }
#pragma unroll
    for (int o = 16; o; o >>= 1) s += __shfl_down_sync(0xffffffffu, s, o);
    __shared__ float red[4];
    if ((threadIdx.x & 31) == 0) red[threadIdx.x >> 5] = s;
    __syncthreads();
    if (threadIdx.x == 0) {
        float t = red[0] + red[1] + red[2] + red[3];
        g_w[row] = (t > 1e-24f) ? 1.0f : 0.5f;   // dist > EPS  <=>  dist^2 > EPS^2
    }
}

__global__ void final_reduce(float* __restrict__ out)
{
    float s = 0.f;
    for (int i = threadIdx.x; i < 24 * 32; i += 256) s += g_lpart[i];
#pragma unroll
    for (int o = 16; o; o >>= 1) s += __shfl_down_sync(0xffffffffu, s, o);
    __shared__ float red[8];
    if ((threadIdx.x & 31) == 0) red[threadIdx.x >> 5] = s;
    __syncthreads();
    if (threadIdx.x == 0) {
        float t = 0.f;
#pragma unroll
        for (int i = 0; i < 8; i++) t += red[i];
        out[0] = t * (1.0f / (float)(BS_ * NN_));
    }
}

// ---------------------------------------------------------------------------
// Launch plan.
//   Key simplification: decoder is a ReLU MLP => piecewise linear => the
//   nested-jvp "hess" term in the reference is exactly zero. So:
//     n_recon[b,n] = recon[b] + J(z_c[b]) . (z_nn[b,n] - z_c[b])
//   with JVP masks taken from the CENTER's pre-activations.
// ---------------------------------------------------------------------------
extern "C" void kernel_launch(void* const* d_in, const int* in_sizes, int n_in,
                              void* d_out, int out_size)
{
    const float* x_c  = (const float*)d_in[0];
    const float* x_nn = (const float*)d_in[1];
    const float* We1  = (const float*)d_in[2];
    const float* be1  = (const float*)d_in[3];
    const float* We2  = (const float*)d_in[4];
    const float* be2  = (const float*)d_in[5];
    const float* We3  = (const float*)d_in[6];
    const float* be3  = (const float*)d_in[7];
    const float* Wd1  = (const float*)d_in[8];
    const float* bd1  = (const float*)d_in[9];
    const float* Wd2  = (const float*)d_in[10];
    const float* bd2  = (const float*)d_in[11];
    const float* Wd3  = (const float*)d_in[12];
    const float* bd3  = (const float*)d_in[13];
    float* out = (float*)d_out;

    float *h1, *h2, *Zb, *dz, *h1c, *h2c, *recon;
    cudaGetSymbolAddress((void**)&h1, g_h1);
    cudaGetSymbolAddress((void**)&h2, g_h2);
    cudaGetSymbolAddress((void**)&Zb, g_Z);
    cudaGetSymbolAddress((void**)&dz, g_dz);
    cudaGetSymbolAddress((void**)&h1c, g_h1c);
    cudaGetSymbolAddress((void**)&h2c, g_h2c);
    cudaGetSymbolAddress((void**)&recon, g_recon);

    const dim3 t(256);

    // Encoder: rows 0..127 = x_c, rows 128..4223 = x_nn (flattened)
    gemm128<1><<<dim3(8, 1), t>>>(x_c,  We1, h1,              be1, nullptr, D_, H_);
    gemm128<1><<<dim3(8, 32), t>>>(x_nn, We1, h1 + BS_ * H_,  be1, nullptr, D_, H_);
    gemm128<1><<<dim3(8, 33), t>>>(h1,   We2, h2,             be2, nullptr, H_, H_);
    fc_skinny32<<<MALL / 8, 256>>>(h2, We3, be3, Zb, H_);

    // dz = z_nn - z_c
    dz_kernel<<<(MNN * Z_) / 256, 256>>>();

    // Center decoder path (activations double as JVP masks)
    gemm128<1><<<dim3(8, 1), t>>>(Zb,  Wd1, h1c,   bd1, nullptr, Z_, H_);
    gemm128<1><<<dim3(8, 1), t>>>(h1c, Wd2, h2c,   bd2, nullptr, H_, H_);
    gemm128<2><<<dim3(24, 1), t>>>(h2c, Wd3, recon, bd3, nullptr, H_, D_);

    // JVP chain (reuse encoder scratch): t_h1 -> g_h1, t_h2 -> g_h2
    gemm128<3><<<dim3(8, 32), t>>>(dz, Wd1, h1, nullptr, h1c, Z_, H_);
    gemm128<3><<<dim3(8, 32), t>>>(h1, Wd2, h2, nullptr, h2c, H_, H_);

    // Binary-kernel weights
    weights_kernel<<<MNN, 128>>>(x_c, x_nn);

    // Final GEMM (jac = t_h2 @ Wd3) with fused weighted squared-error loss
    gemm128_loss<<<dim3(24, 32), t>>>(h2, Wd3, x_nn, recon, H_, D_);
    final_reduce<<<1, 256>>>(out);
}